// round 13
// baseline (speedup 1.0000x reference)
#include <cuda_runtime.h>

// Problem: B=4, T=4096, WINDOW=1024, MAX_DISP=2.0
// out[b,t] = linear interp of x at s = w[b]*coeff[t] + t (tent kernel collapses),
// out-of-range k dropped.
//
// Latency-bound at the single-launch floor. R13 experiment: remove smem/BAR
// entirely — per-warp register window + shuffle select. Each lane prefetches
// x[wt0-16+lane] and x[wt0+16+lane] (overlapped with the w float4 load); the
// dependent read is 2 SHFL + SEL, no barrier of any scope. A single
// warp-uniform branch guards the |disp|<13 window; the cold path is the fully
// generic global-load version (never taken for these inputs).

#define T_DIM 4096
#define B_DIM 4
#define BLK   128                // 4 warps/block; 32 blocks; t-range 128/block
#define FULL_MASK 0xFFFFFFFFu

__global__ void __launch_bounds__(BLK) tvp_kernel(const float4* __restrict__ w4,
                                                  const float* __restrict__ x,
                                                  float* __restrict__ out) {
    const int tid  = threadIdx.x;
    const int lane = tid & 31;
    const int t    = blockIdx.x * BLK + tid;   // 0 .. T-1
    const int wt0  = t - lane;                 // warp's first t

    // --- issue all independent loads up front (overlap, no smem, no BAR) ---
    float4 wv = __ldg(w4);                     // all 4 w's, one 16B line, broadcast

    // register window covering [wt0-16, wt0+48), clamped addresses
    int c0 = min(max(wt0 - 16 + lane, 0), T_DIM - 1);
    int c1 = min(max(wt0 + 16 + lane, 0), T_DIM - 1);
    float v0 = x[c0];                          // independent of w -> overlaps
    float v1 = x[c1];

    // --- dependent math ---
    // coeff = 2*((t mod 1024)/1024 - 0.5) == (t mod 1024)/512 - 1, exact in fp32
    float wn = (float)(t & 1023);
    float c  = fmaf(wn, 1.0f / 512.0f, -1.0f); // single FFMA-imm, bit-exact
    float tf = (float)t;

    const float wb[4] = {wv.x, wv.y, wv.z, wv.w};

    float maxw = fmaxf(fmaxf(fabsf(wv.x), fabsf(wv.y)),
                       fmaxf(fabsf(wv.z), fabsf(wv.w)));

    if (maxw < 13.0f) {                        // warp-uniform: |disp| <= maxw < 13
        #pragma unroll
        for (int b = 0; b < B_DIM; b++) {
            float s    = wb[b] * c + tf;       // match reference mul-then-add
            int   k0   = __float2int_rd(s);
            float frac = s - (float)k0;
            int   k1   = k0 + 1;

            // exact k-range enforcement via weight masks (FSEL, no branch)
            float m0 = (k0 >= 0 && k0 < T_DIM) ? (1.0f - frac) : 0.0f;
            float m1 = (k1 >= 0 && k1 < T_DIM) ? frac          : 0.0f;

            // window index: i = k - (wt0-16) in [lane+16-13, lane+16+14] ⊂ [3,62]
            int i0 = k0 - wt0 + 16;
            int i1 = i0 + 1;

            // shuffle-select from the warp register window (no memory access)
            float a0 = __shfl_sync(FULL_MASK, v0, i0);        // valid when i0<32
            float b0 = __shfl_sync(FULL_MASK, v1, i0 - 32);   // valid when i0>=32
            float a1 = __shfl_sync(FULL_MASK, v0, i1);
            float b1 = __shfl_sync(FULL_MASK, v1, i1 - 32);
            float val0 = (i0 < 32) ? a0 : b0;
            float val1 = (i1 < 32) ? a1 : b1;

            out[b * T_DIM + t] = fmaf(m0, val0, m1 * val1);   // coalesced
        }
    } else {                                   // generic fallback, never taken here
        #pragma unroll
        for (int b = 0; b < B_DIM; b++) {
            float s    = wb[b] * c + tf;
            int   k0   = __float2int_rd(s);
            float frac = s - (float)k0;
            int   k1   = k0 + 1;

            float acc = 0.0f;
            if (k0 >= 0 && k0 < T_DIM) acc += (1.0f - frac) * x[k0];
            if (k1 >= 0 && k1 < T_DIM) acc += frac * x[k1];
            out[b * T_DIM + t] = acc;
        }
    }
}

extern "C" void kernel_launch(void* const* d_in, const int* in_sizes, int n_in,
                              void* d_out, int out_size) {
    const float4* w4 = (const float4*)d_in[0];  // [4,1] -> one float4
    const float*  x  = (const float*)d_in[1];   // [1,4096]
    float* out = (float*)d_out;                 // [4,4096,1] = 16384 floats

    const int blocks = T_DIM / BLK;             // 32
    tvp_kernel<<<blocks, BLK>>>(w4, x, out);
}

// round 14
// speedup vs baseline: 1.2386x; 1.2386x over previous
#include <cuda_runtime.h>

// Problem: B=4, T=4096, WINDOW=1024, MAX_DISP=2.0
// out[b,t] = linear interp of x at s = w[b]*coeff[t] + t (tent kernel collapses),
// out-of-range k dropped.
//
// FINAL KERNEL — converged over 13 measured rounds; latency-bound at the
// single-launch floor (all ncu pipes <0.5%, DRAM 0.1%). Design-space map,
// every point measured with a predicted delta:
//   smem tile + BAR + LDS (this)      : 3.97-4.26 us ncu  <- best
//   smem tile + warp-scope sync (R11) : 4.22 (barrier scope irrelevant)
//   register window + SHFL (R13)      : 5.31 (shuffles cost more than LDS)
//   warp tiles w/ extra instrs (R3)   : 4.48 (instruction count rules)
//   scalar 2-LDG direct (R1)          : 4.74 (serialized DRAM round trips)
// Mechanisms in this kernel:
//  - analytic collapse of the [4,4096,4096] tent-kernel matmul to 2-tap interp
//  - w (float4) load overlapped with the w-independent x-tile prefetch:
//    the two cold-DRAM round trips run concurrently (-0.8us, R2)
//  - grid=32 x 128: one block-wide tile serves all 4 batch rows (R6)
//  - branchless epilogue: FSEL weight masks enforce exact k in [0,T)
//    semantics; clamped smem indices give unconditional memory safety (R7)
//  - coeff folded to one bit-exact FFMA-imm; per-chain stores (R8/R9)

#define T_DIM 4096
#define B_DIM 4
#define BLK   128                // t-range per block = 128; 32 blocks total
#define HALO  64                 // |w*coeff| << 64 for these inputs
#define TILE  (BLK + 2 * HALO)   // 256 floats = 1 KB shared

__global__ void __launch_bounds__(BLK) tvp_kernel(const float4* __restrict__ w4,
                                                  const float* __restrict__ x,
                                                  float* __restrict__ out) {
    __shared__ float sx[TILE];

    const int tid  = threadIdx.x;
    const int t    = blockIdx.x * BLK + tid;   // 0 .. T-1
    const int t0   = t - tid;                  // block's first t
    const int base = t0 - HALO;                // tile covers k in [base, base+TILE)

    // --- issue all independent loads up front (overlap) ---
    float4 wv = __ldg(w4);                     // all 4 w's, one 16B line, broadcast

    {   // cooperative x tile prefetch: 2 coalesced floats per thread, clamped
        int ca = min(max(base + tid,       0), T_DIM - 1);
        int cb = min(max(base + tid + BLK, 0), T_DIM - 1);
        float va = x[ca];                      // independent of w -> overlaps
        float vb = x[cb];
        sx[tid]       = va;
        sx[tid + BLK] = vb;
    }
    __syncthreads();

    // --- dependent math: 4 independent, fully branchless interp chains ---
    // coeff = 2*((t mod 1024)/1024 - 0.5) == (t mod 1024)/512 - 1, exact in fp32
    float wn = (float)(t & 1023);
    float c  = fmaf(wn, 1.0f / 512.0f, -1.0f); // single FFMA-imm, bit-exact
    float tf = (float)t;

    const float wb[4] = {wv.x, wv.y, wv.z, wv.w};

    #pragma unroll
    for (int b = 0; b < B_DIM; b++) {
        float s    = wb[b] * c + tf;           // match reference mul-then-add
        int   k0   = __float2int_rd(s);
        float frac = s - (float)k0;
        int   k1   = k0 + 1;

        // exact k-range enforcement via weight masks (FSEL, no branch)
        float m0 = (k0 >= 0 && k0 < T_DIM) ? (1.0f - frac) : 0.0f;
        float m1 = (k1 >= 0 && k1 < T_DIM) ? frac          : 0.0f;

        // tile reads with clamped smem index (always a valid address)
        int o0 = min(max(k0 - base, 0), TILE - 1);
        int o1 = min(max(k1 - base, 0), TILE - 1);

        // store as soon as this chain resolves (coalesced per warp)
        out[b * T_DIM + t] = fmaf(m0, sx[o0], m1 * sx[o1]);
    }
}

extern "C" void kernel_launch(void* const* d_in, const int* in_sizes, int n_in,
                              void* d_out, int out_size) {
    const float4* w4 = (const float4*)d_in[0];  // [4,1] -> one float4
    const float*  x  = (const float*)d_in[1];   // [1,4096]
    float* out = (float*)d_out;                 // [4,4096,1] = 16384 floats

    const int blocks = T_DIM / BLK;             // 32
    tvp_kernel<<<blocks, BLK>>>(w4, x, out);
}

// round 15
// speedup vs baseline: 1.4437x; 1.1656x over previous
#include <cuda_runtime.h>

// Problem: B=4, T=4096, WINDOW=1024, MAX_DISP=2.0
// out[b,t] = linear interp of x at s = w[b]*coeff[t] + t (tent kernel collapses),
// out-of-range k dropped.
//
// Latency-bound at the single-launch floor. R15 experiment: vectorized stores.
// Warp w owns batch row w; each thread emits 4 consecutive t as one STG.128
// (was 4x STG.32). Upstream structure identical to the converged best:
// overlapped w/tile loads, block-wide tile, branchless FSEL epilogue.

#define T_DIM 4096
#define B_DIM 4
#define BLK   128                // 4 warps = 4 batch rows; 32 blocks; 128 t/block
#define HALO  64                 // |w*coeff| << 64 for these inputs
#define TILE  (BLK + 2 * HALO)   // 256 floats = 1 KB shared

__global__ void __launch_bounds__(BLK) tvp_kernel(const float4* __restrict__ w4,
                                                  const float* __restrict__ x,
                                                  float4* __restrict__ out4) {
    __shared__ float sx[TILE];

    const int tid  = threadIdx.x;
    const int wid  = tid >> 5;                 // warp id == batch row b
    const int lane = tid & 31;
    const int t0   = blockIdx.x * BLK;         // block's first t (mult of 128)
    const int base = t0 - HALO;                // tile covers k in [base, base+TILE)
    const int tt   = t0 + (lane << 2);         // this thread's first t (4 consecutive)

    // --- issue all independent loads up front (overlap) ---
    float4 wv = __ldg(w4);                     // all 4 w's, one 16B line, broadcast

    {   // cooperative x tile prefetch: 2 coalesced floats per thread, clamped
        int ca = min(max(base + tid,       0), T_DIM - 1);
        int cb = min(max(base + tid + BLK, 0), T_DIM - 1);
        float va = x[ca];                      // independent of w -> overlaps
        float vb = x[cb];
        sx[tid]       = va;
        sx[tid + BLK] = vb;
    }
    __syncthreads();

    // warp-uniform batch weight (SEL chain, no memory access)
    float wb = (wid == 0) ? wv.x : (wid == 1) ? wv.y : (wid == 2) ? wv.z : wv.w;

    // --- dependent math: 4 independent, fully branchless interp chains ---
    float r[4];

    #pragma unroll
    for (int j = 0; j < 4; j++) {
        int   t    = tt + j;
        // coeff = (t mod 1024)/512 - 1, exact in fp32 (single FFMA-imm)
        float wn   = (float)(t & 1023);
        float c    = fmaf(wn, 1.0f / 512.0f, -1.0f);
        float s    = wb * c + (float)t;        // match reference mul-then-add
        int   k0   = __float2int_rd(s);
        float frac = s - (float)k0;
        int   k1   = k0 + 1;

        // exact k-range enforcement via weight masks (FSEL, no branch)
        float m0 = (k0 >= 0 && k0 < T_DIM) ? (1.0f - frac) : 0.0f;
        float m1 = (k1 >= 0 && k1 < T_DIM) ? frac          : 0.0f;

        // tile reads with clamped smem index (always a valid address)
        int o0 = min(max(k0 - base, 0), TILE - 1);
        int o1 = min(max(k1 - base, 0), TILE - 1);

        r[j] = fmaf(m0, sx[o0], m1 * sx[o1]);
    }

    // one STG.128 per thread, coalesced across the warp (128 floats per row)
    out4[(wid * T_DIM + tt) >> 2] = make_float4(r[0], r[1], r[2], r[3]);
}

extern "C" void kernel_launch(void* const* d_in, const int* in_sizes, int n_in,
                              void* d_out, int out_size) {
    const float4* w4 = (const float4*)d_in[0];  // [4,1] -> one float4
    const float*  x  = (const float*)d_in[1];   // [1,4096]
    float4* out = (float4*)d_out;               // [4,4096,1], 16B-aligned

    const int blocks = T_DIM / BLK;             // 32
    tvp_kernel<<<blocks, BLK>>>(w4, x, out);
}